// round 3
// baseline (speedup 1.0000x reference)
#include <cuda_runtime.h>
#include <math.h>

#define B_ 256
#define N_ 31
#define G_ 32
#define T_ 64
#define H_ 128
#define GT_ 2048          // G_*T_
#define XPAD 132
#define QPAD 132

// Scratch (device globals are the allowed scratch mechanism)
__device__ float g_Q[(size_t)B_ * T_ * H_];          // 8 MB
__device__ float g_Kt[(size_t)B_ * H_ * GT_];        // 256 MB, layout [b][h][key]
__device__ float g_V[(size_t)B_ * GT_ * H_];         // 256 MB, layout [b][key][h]
__device__ int   g_maskKind;                         // 0=u8/bool, 1=int32, 2=float32

// ---------------------------------------------------------------------------
// Mask dtype sniffer: deterministic function of the input bytes.
// int32 0/1 words == {0,1}; float32 0/1 words == {0x0, 0x3F800000};
// random bool bytes form words matching neither.
// ---------------------------------------------------------------------------
__global__ void k_detect_mask(const unsigned* __restrict__ m) {
    __shared__ int okInt, okFloat;
    if (threadIdx.x == 0) { okInt = 1; okFloat = 1; }
    __syncthreads();
    int badI = 0, badF = 0;
    for (int i = threadIdx.x; i < 1024; i += 256) {
        unsigned w = m[i];
        if (!(w == 0u || w == 1u)) badI = 1;
        if (!(w == 0u || w == 0x3F800000u)) badF = 1;
    }
    if (badI) atomicAnd(&okInt, 0);
    if (badF) atomicAnd(&okFloat, 0);
    __syncthreads();
    if (threadIdx.x == 0)
        g_maskKind = okInt ? 1 : (okFloat ? 2 : 0);
}

// ---------------------------------------------------------------------------
// Kernel 0: Q = node @ Wq.  One CTA per batch. smem: Wq[128][128] + X[64][XPAD]
// ---------------------------------------------------------------------------
__global__ void __launch_bounds__(256)
k_qproj(const float* __restrict__ node, const float* __restrict__ Wq) {
    extern __shared__ float sm[];
    float* ws = sm;                 // [128][128]
    float* xs = sm + H_ * H_;       // [64][XPAD]
    const int b = blockIdx.x;
    const int tid = threadIdx.x;

    for (int f = tid; f < H_ * H_ / 4; f += 256) {
        int k = f >> 5, j4 = f & 31;
        float4 v = ((const float4*)Wq)[f];
        *(float4*)&ws[k * H_ + j4 * 4] = v;
    }
    const float* src = node + (size_t)b * T_ * H_;
    for (int f = tid; f < T_ * H_ / 4; f += 256) {
        int r = f >> 5, h4 = f & 31;
        float4 v = ((const float4*)src)[f];
        *(float4*)&xs[r * XPAD + h4 * 4] = v;
    }
    __syncthreads();

    const int trow = tid >> 5;   // 8 row groups * 8 rows
    const int tcol = tid & 31;   // 32 col groups * 4 cols
    float acc[8][4];
#pragma unroll
    for (int i = 0; i < 8; i++)
#pragma unroll
        for (int j = 0; j < 4; j++) acc[i][j] = 0.f;

    for (int k0 = 0; k0 < H_; k0 += 4) {
        float xr[8][4];
#pragma unroll
        for (int i = 0; i < 8; i++) {
            float4 v = *(float4*)&xs[(trow * 8 + i) * XPAD + k0];
            xr[i][0] = v.x; xr[i][1] = v.y; xr[i][2] = v.z; xr[i][3] = v.w;
        }
#pragma unroll
        for (int kk = 0; kk < 4; kk++) {
            float4 w = *(float4*)&ws[(k0 + kk) * H_ + tcol * 4];
#pragma unroll
            for (int i = 0; i < 8; i++) {
                acc[i][0] += xr[i][kk] * w.x;
                acc[i][1] += xr[i][kk] * w.y;
                acc[i][2] += xr[i][kk] * w.z;
                acc[i][3] += xr[i][kk] * w.w;
            }
        }
    }
#pragma unroll
    for (int i = 0; i < 8; i++) {
        int row = trow * 8 + i;
        float4 v = make_float4(acc[i][0], acc[i][1], acc[i][2], acc[i][3]);
        *(float4*)&g_Q[((size_t)b * T_ + row) * H_ + tcol * 4] = v;
    }
}

// ---------------------------------------------------------------------------
// Kernel 1: K^T and V projections for kv_src = concat(node, neigh).
// Grid (8, B): blockIdx.x = 4-group segment, blockIdx.y = batch.
// smem: W[128][256] (Wk cols 0..127, Wv cols 128..255) + X[64][XPAD]
// ---------------------------------------------------------------------------
__global__ void __launch_bounds__(256)
k_kvproj(const float* __restrict__ node, const float* __restrict__ neigh,
         const float* __restrict__ Wk, const float* __restrict__ Wv) {
    extern __shared__ float sm[];
    float* ws = sm;                 // [128][256]
    float* xs = sm + H_ * 256;      // [64][XPAD], reused as K-transpose staging
    const int b = blockIdx.y;
    const int seg = blockIdx.x;     // groups seg*4 .. seg*4+3
    const int tid = threadIdx.x;

    for (int f = tid; f < H_ * H_ / 4; f += 256) {
        int k = f >> 5, j4 = f & 31;
        float4 vk = ((const float4*)Wk)[f];
        float4 vv = ((const float4*)Wv)[f];
        *(float4*)&ws[k * 256 + j4 * 4] = vk;
        *(float4*)&ws[k * 256 + 128 + j4 * 4] = vv;
    }

    const int trow = tid >> 5;   // 8 groups * 8 rows (keys)
    const int tcol = tid & 31;   // 32 groups * 8 cols

    for (int gi = 0; gi < 4; gi++) {
        const int g = seg * 4 + gi;
        __syncthreads();  // W staged (gi=0) / previous transpose reads done
        const float* src = (g == 0)
            ? (node + (size_t)b * T_ * H_)
            : (neigh + (((size_t)b * N_ + (g - 1)) * T_) * H_);
        for (int f = tid; f < T_ * H_ / 4; f += 256) {
            int r = f >> 5, h4 = f & 31;
            float4 v = ((const float4*)src)[f];
            *(float4*)&xs[r * XPAD + h4 * 4] = v;
        }
        __syncthreads();

        float acc[8][8];
#pragma unroll
        for (int i = 0; i < 8; i++)
#pragma unroll
            for (int j = 0; j < 8; j++) acc[i][j] = 0.f;

        for (int k0 = 0; k0 < H_; k0 += 4) {
            float xr[8][4];
#pragma unroll
            for (int i = 0; i < 8; i++) {
                float4 v = *(float4*)&xs[(trow * 8 + i) * XPAD + k0];
                xr[i][0] = v.x; xr[i][1] = v.y; xr[i][2] = v.z; xr[i][3] = v.w;
            }
#pragma unroll
            for (int kk = 0; kk < 4; kk++) {
                float4 w0 = *(float4*)&ws[(k0 + kk) * 256 + tcol * 8];
                float4 w1 = *(float4*)&ws[(k0 + kk) * 256 + tcol * 8 + 4];
                float wr[8] = {w0.x, w0.y, w0.z, w0.w, w1.x, w1.y, w1.z, w1.w};
#pragma unroll
                for (int i = 0; i < 8; i++)
#pragma unroll
                    for (int j = 0; j < 8; j++)
                        acc[i][j] += xr[i][kk] * wr[j];
            }
        }

        // V (cols 128..255): direct row-major store
        if (tcol >= 16) {
            const int hb = (tcol - 16) * 8;
#pragma unroll
            for (int i = 0; i < 8; i++) {
                size_t key = (size_t)g * T_ + trow * 8 + i;
                float* dst = &g_V[((size_t)b * GT_ + key) * H_ + hb];
                *(float4*)dst       = make_float4(acc[i][0], acc[i][1], acc[i][2], acc[i][3]);
                *(float4*)(dst + 4) = make_float4(acc[i][4], acc[i][5], acc[i][6], acc[i][7]);
            }
        }
        __syncthreads();  // xs reads (compute) complete -> safe to reuse as staging
        // K (cols 0..127): stage into xs, then write transposed
        if (tcol < 16) {
#pragma unroll
            for (int i = 0; i < 8; i++)
#pragma unroll
                for (int j = 0; j < 8; j++)
                    xs[(trow * 8 + i) * XPAD + tcol * 8 + j] = acc[i][j];
        }
        __syncthreads();
        for (int idx = tid; idx < T_ * H_; idx += 256) {
            int h = idx >> 6;       // 0..127
            int key = idx & 63;     // 0..63 (coalesced)
            g_Kt[((size_t)b * H_ + h) * GT_ + (size_t)g * T_ + key] = xs[key * XPAD + h];
        }
    }
}

// ---------------------------------------------------------------------------
// Kernel 2: attention per batch.  256 threads, ~105 KB smem -> 2 CTAs/SM.
// Phase A: S = Q K^T per 128-key chunk, mask->-inf, write raw S to A region,
//          accumulate rowsum of exp(S) (no max subtraction: |S| <= ~63, safe).
// Phase C: re-read S, write P = exp(S)/l, accumulate O = P V, write O.
// ---------------------------------------------------------------------------
__global__ void __launch_bounds__(256, 2)
k_attn(const void* __restrict__ mask, float* __restrict__ out) {
    extern __shared__ float sm[];
    float* qs = sm;                          // [64][QPAD]  (phase C: P tile)
    float* ks = sm + T_ * QPAD;              // [128][128]  (phase C: V tile)
    float* red = ks + H_ * H_;               // [64*16]
    float* invl = red + T_ * 16;             // [64]
    unsigned char* ms = (unsigned char*)(invl + T_);  // [64*64]

    const int b = blockIdx.x;
    const int tid = threadIdx.x;
    const int tq = tid >> 4;   // 16 groups * 4 q rows
    const int tk = tid & 15;   // 16 groups * 8 keys (phase A) / 8 h (phase C)

    float* Ab = out + (size_t)B_ * T_ * H_ + (size_t)b * T_ * GT_;

    // Stage Q and mask (mask dtype per g_maskKind)
    const float* qg = g_Q + (size_t)b * T_ * H_;
    for (int f = tid; f < T_ * H_ / 4; f += 256) {
        int r = f >> 5, h4 = f & 31;
        *(float4*)&qs[r * QPAD + h4 * 4] = ((const float4*)qg)[f];
    }
    {
        const size_t base = (size_t)b * T_ * T_;
        const int kind = g_maskKind;
        if (kind == 1) {
            const int* mg = (const int*)mask + base;
            for (int f = tid; f < T_ * T_; f += 256)
                ms[f] = (unsigned char)(mg[f] != 0);
        } else if (kind == 2) {
            const float* mg = (const float*)mask + base;
            for (int f = tid; f < T_ * T_; f += 256)
                ms[f] = (unsigned char)(mg[f] != 0.0f);
        } else {
            const unsigned char* mg = (const unsigned char*)mask + base;
            for (int f = tid; f < T_ * T_; f += 256)
                ms[f] = mg[f];
        }
    }
    __syncthreads();

    // Per-thread mask bits: key-in-chunk = tk*8+j, mask col = (tk*8+j) % 64,
    // identical for every chunk (chunk size 128 = 2*T_).
    unsigned mbits[4];
#pragma unroll
    for (int i = 0; i < 4; i++) {
        int q = tq * 4 + i;
        unsigned m = 0;
#pragma unroll
        for (int j = 0; j < 8; j++) {
            int col = (tk * 8 + j) & 63;
            if (ms[q * 64 + col]) m |= (1u << j);
        }
        mbits[i] = m;
    }

    const float NEG_INF = __int_as_float(0xff800000u);
    float lsum[4] = {0.f, 0.f, 0.f, 0.f};
    const float* ktg = g_Kt + (size_t)b * H_ * GT_;

    for (int c = 0; c < 16; c++) {
        __syncthreads();
        for (int f = tid; f < H_ * 128 / 4; f += 256) {
            int h = f >> 5, k4 = f & 31;
            *(float4*)&ks[h * 128 + k4 * 4] =
                *(const float4*)&ktg[(size_t)h * GT_ + c * 128 + k4 * 4];
        }
        __syncthreads();

        float sc[4][8];
#pragma unroll
        for (int i = 0; i < 4; i++)
#pragma unroll
            for (int j = 0; j < 8; j++) sc[i][j] = 0.f;

        for (int h0 = 0; h0 < H_; h0 += 4) {
            float qr[4][4];
#pragma unroll
            for (int i = 0; i < 4; i++) {
                float4 v = *(float4*)&qs[(tq * 4 + i) * QPAD + h0];
                qr[i][0] = v.x; qr[i][1] = v.y; qr[i][2] = v.z; qr[i][3] = v.w;
            }
#pragma unroll
            for (int hh = 0; hh < 4; hh++) {
                float4 k0v = *(float4*)&ks[(h0 + hh) * 128 + tk * 8];
                float4 k1v = *(float4*)&ks[(h0 + hh) * 128 + tk * 8 + 4];
                float kr[8] = {k0v.x, k0v.y, k0v.z, k0v.w, k1v.x, k1v.y, k1v.z, k1v.w};
#pragma unroll
                for (int i = 0; i < 4; i++)
#pragma unroll
                    for (int j = 0; j < 8; j++)
                        sc[i][j] += qr[i][hh] * kr[j];
            }
        }
#pragma unroll
        for (int i = 0; i < 4; i++) {
            int q = tq * 4 + i;
#pragma unroll
            for (int j = 0; j < 8; j++) {
                if ((mbits[i] >> j) & 1) sc[i][j] = NEG_INF;
                lsum[i] += __expf(sc[i][j]);
            }
            float* dst = &Ab[(size_t)q * GT_ + c * 128 + tk * 8];
            *(float4*)dst       = make_float4(sc[i][0], sc[i][1], sc[i][2], sc[i][3]);
            *(float4*)(dst + 4) = make_float4(sc[i][4], sc[i][5], sc[i][6], sc[i][7]);
        }
    }

    // Row-sum reduction -> 1/l
#pragma unroll
    for (int i = 0; i < 4; i++) red[(tq * 4 + i) * 16 + tk] = lsum[i];
    __syncthreads();
    if (tid < 64) {
        float s = 0.f;
#pragma unroll
        for (int t = 0; t < 16; t++) s += red[tid * 16 + t];
        invl[tid] = 1.0f / s;
    }

    // ---------------- Phase C ----------------
    float* ps = qs;   // reuse Q tile as P tile
    float* vs = ks;   // reuse K tile as V tile
    const float* vg = g_V + (size_t)b * GT_ * H_;
    const int th = tk;

    float oacc[4][8];
#pragma unroll
    for (int i = 0; i < 4; i++)
#pragma unroll
        for (int j = 0; j < 8; j++) oacc[i][j] = 0.f;

    for (int c = 0; c < 16; c++) {
        __syncthreads();
        for (int f = tid; f < 128 * H_ / 4; f += 256) {
            int key = f >> 5, h4 = f & 31;
            *(float4*)&vs[key * 128 + h4 * 4] =
                *(const float4*)&vg[((size_t)(c * 128 + key)) * H_ + h4 * 4];
        }
        for (int f = tid; f < T_ * 128 / 4; f += 256) {
            int q = f >> 5, k4 = f & 31;
            float* gaddr = &Ab[(size_t)q * GT_ + c * 128 + k4 * 4];
            float4 v = *(float4*)gaddr;
            float il = invl[q];
            v.x = __expf(v.x) * il;
            v.y = __expf(v.y) * il;
            v.z = __expf(v.z) * il;
            v.w = __expf(v.w) * il;
            *(float4*)gaddr = v;
            *(float4*)&ps[q * QPAD + k4 * 4] = v;
        }
        __syncthreads();

        for (int kk0 = 0; kk0 < 128; kk0 += 4) {
            float pr[4][4];
#pragma unroll
            for (int i = 0; i < 4; i++) {
                float4 v = *(float4*)&ps[(tq * 4 + i) * QPAD + kk0];
                pr[i][0] = v.x; pr[i][1] = v.y; pr[i][2] = v.z; pr[i][3] = v.w;
            }
#pragma unroll
            for (int u = 0; u < 4; u++) {
                float4 v0 = *(float4*)&vs[(kk0 + u) * 128 + th * 8];
                float4 v1 = *(float4*)&vs[(kk0 + u) * 128 + th * 8 + 4];
                float vr[8] = {v0.x, v0.y, v0.z, v0.w, v1.x, v1.y, v1.z, v1.w};
#pragma unroll
                for (int i = 0; i < 4; i++)
#pragma unroll
                    for (int j = 0; j < 8; j++)
                        oacc[i][j] += pr[i][u] * vr[j];
            }
        }
    }

#pragma unroll
    for (int i = 0; i < 4; i++) {
        int q = tq * 4 + i;
        float* dst = &out[((size_t)b * T_ + q) * H_ + th * 8];
        *(float4*)dst       = make_float4(oacc[i][0], oacc[i][1], oacc[i][2], oacc[i][3]);
        *(float4*)(dst + 4) = make_float4(oacc[i][4], oacc[i][5], oacc[i][6], oacc[i][7]);
    }
}

// ---------------------------------------------------------------------------
static const int SMEM_Q  = (H_ * H_ + T_ * XPAD) * 4;                 //  99328
static const int SMEM_KV = (H_ * 256 + T_ * XPAD) * 4;                // 164864
static const int SMEM_AT = (T_ * QPAD + H_ * H_ + T_ * 16 + T_) * 4 + T_ * T_; // 107776

extern "C" void kernel_launch(void* const* d_in, const int* in_sizes, int n_in,
                              void* d_out, int out_size) {
    (void)in_sizes; (void)n_in; (void)out_size;
    const float* node  = (const float*)d_in[0];
    const float* neigh = (const float*)d_in[1];
    const void*  mask  = d_in[2];
    const float* Wq = (const float*)d_in[3];
    const float* Wk = (const float*)d_in[4];
    const float* Wv = (const float*)d_in[5];
    float* out = (float*)d_out;

    // One-time attribute opt-in (first call happens before graph capture).
    static bool inited = false;
    if (!inited) {
        cudaFuncSetAttribute(k_qproj,  cudaFuncAttributeMaxDynamicSharedMemorySize, SMEM_Q);
        cudaFuncSetAttribute(k_kvproj, cudaFuncAttributeMaxDynamicSharedMemorySize, SMEM_KV);
        cudaFuncSetAttribute(k_attn,   cudaFuncAttributeMaxDynamicSharedMemorySize, SMEM_AT);
        inited = true;
    }

    k_detect_mask<<<1, 256>>>((const unsigned*)mask);
    k_qproj<<<B_, 256, SMEM_Q>>>(node, Wq);
    k_kvproj<<<dim3(8, B_), 256, SMEM_KV>>>(node, neigh, Wk, Wv);
    k_attn<<<B_, 256, SMEM_AT>>>(mask, out);
}

// round 5
// speedup vs baseline: 1.0079x; 1.0079x over previous
#include <cuda_runtime.h>
#include <math.h>

#define B_ 256
#define N_ 31
#define G_ 32
#define T_ 64
#define H_ 128
#define GT_ 2048          // G_*T_
#define XPAD 132
#define QPAD 132

// Scratch (device globals are the allowed scratch mechanism)
__device__ float g_Q[(size_t)B_ * T_ * H_];          // 8 MB
__device__ float g_Kt[(size_t)B_ * H_ * GT_];        // 256 MB, layout [b][h][key]
__device__ float g_V[(size_t)B_ * GT_ * H_];         // 256 MB, layout [b][key][h]
__device__ int   g_maskKind;                         // 0=u8/bool, 1=int32, 2=float32

// ---------------------------------------------------------------------------
// Mask dtype sniffer: deterministic function of the input bytes.
// int32 0/1 words == {0,1}; float32 0/1 words == {0x0, 0x3F800000};
// random bool bytes form words matching neither.
// ---------------------------------------------------------------------------
__global__ void k_detect_mask(const unsigned* __restrict__ m) {
    __shared__ int okInt, okFloat;
    if (threadIdx.x == 0) { okInt = 1; okFloat = 1; }
    __syncthreads();
    int badI = 0, badF = 0;
    for (int i = threadIdx.x; i < 1024; i += 256) {
        unsigned w = m[i];
        if (!(w == 0u || w == 1u)) badI = 1;
        if (!(w == 0u || w == 0x3F800000u)) badF = 1;
    }
    if (badI) atomicAnd(&okInt, 0);
    if (badF) atomicAnd(&okFloat, 0);
    __syncthreads();
    if (threadIdx.x == 0)
        g_maskKind = okInt ? 1 : (okFloat ? 2 : 0);
}

// ---------------------------------------------------------------------------
// Kernel 0: Q = node @ Wq.  One CTA per batch. smem: Wq[128][128] + X[64][XPAD]
// ---------------------------------------------------------------------------
__global__ void __launch_bounds__(256)
k_qproj(const float* __restrict__ node, const float* __restrict__ Wq) {
    extern __shared__ float sm[];
    float* ws = sm;                 // [128][128]
    float* xs = sm + H_ * H_;       // [64][XPAD]
    const int b = blockIdx.x;
    const int tid = threadIdx.x;

    for (int f = tid; f < H_ * H_ / 4; f += 256) {
        int k = f >> 5, j4 = f & 31;
        float4 v = ((const float4*)Wq)[f];
        *(float4*)&ws[k * H_ + j4 * 4] = v;
    }
    const float* src = node + (size_t)b * T_ * H_;
    for (int f = tid; f < T_ * H_ / 4; f += 256) {
        int r = f >> 5, h4 = f & 31;
        float4 v = ((const float4*)src)[f];
        *(float4*)&xs[r * XPAD + h4 * 4] = v;
    }
    __syncthreads();

    const int trow = tid >> 5;   // 8 row groups * 8 rows
    const int tcol = tid & 31;   // 32 col groups * 4 cols
    float acc[8][4];
#pragma unroll
    for (int i = 0; i < 8; i++)
#pragma unroll
        for (int j = 0; j < 4; j++) acc[i][j] = 0.f;

    for (int k0 = 0; k0 < H_; k0 += 4) {
        float xr[8][4];
#pragma unroll
        for (int i = 0; i < 8; i++) {
            float4 v = *(float4*)&xs[(trow * 8 + i) * XPAD + k0];
            xr[i][0] = v.x; xr[i][1] = v.y; xr[i][2] = v.z; xr[i][3] = v.w;
        }
#pragma unroll
        for (int kk = 0; kk < 4; kk++) {
            float4 w = *(float4*)&ws[(k0 + kk) * H_ + tcol * 4];
#pragma unroll
            for (int i = 0; i < 8; i++) {
                acc[i][0] += xr[i][kk] * w.x;
                acc[i][1] += xr[i][kk] * w.y;
                acc[i][2] += xr[i][kk] * w.z;
                acc[i][3] += xr[i][kk] * w.w;
            }
        }
    }
#pragma unroll
    for (int i = 0; i < 8; i++) {
        int row = trow * 8 + i;
        float4 v = make_float4(acc[i][0], acc[i][1], acc[i][2], acc[i][3]);
        *(float4*)&g_Q[((size_t)b * T_ + row) * H_ + tcol * 4] = v;
    }
}

// ---------------------------------------------------------------------------
// Kernel 1: K^T and V projections for kv_src = concat(node, neigh).
// Grid (8, B): blockIdx.x = 4-group segment, blockIdx.y = batch.
// smem: W[128][256] (Wk cols 0..127, Wv cols 128..255) + X[64][XPAD]
// ---------------------------------------------------------------------------
__global__ void __launch_bounds__(256)
k_kvproj(const float* __restrict__ node, const float* __restrict__ neigh,
         const float* __restrict__ Wk, const float* __restrict__ Wv) {
    extern __shared__ float sm[];
    float* ws = sm;                 // [128][256]
    float* xs = sm + H_ * 256;      // [64][XPAD], reused as K-transpose staging
    const int b = blockIdx.y;
    const int seg = blockIdx.x;     // groups seg*4 .. seg*4+3
    const int tid = threadIdx.x;

    for (int f = tid; f < H_ * H_ / 4; f += 256) {
        int k = f >> 5, j4 = f & 31;
        float4 vk = ((const float4*)Wk)[f];
        float4 vv = ((const float4*)Wv)[f];
        *(float4*)&ws[k * 256 + j4 * 4] = vk;
        *(float4*)&ws[k * 256 + 128 + j4 * 4] = vv;
    }

    const int trow = tid >> 5;   // 8 groups * 8 rows (keys)
    const int tcol = tid & 31;   // 32 groups * 8 cols

    for (int gi = 0; gi < 4; gi++) {
        const int g = seg * 4 + gi;
        __syncthreads();  // W staged (gi=0) / previous transpose reads done
        const float* src = (g == 0)
            ? (node + (size_t)b * T_ * H_)
            : (neigh + (((size_t)b * N_ + (g - 1)) * T_) * H_);
        for (int f = tid; f < T_ * H_ / 4; f += 256) {
            int r = f >> 5, h4 = f & 31;
            float4 v = ((const float4*)src)[f];
            *(float4*)&xs[r * XPAD + h4 * 4] = v;
        }
        __syncthreads();

        float acc[8][8];
#pragma unroll
        for (int i = 0; i < 8; i++)
#pragma unroll
            for (int j = 0; j < 8; j++) acc[i][j] = 0.f;

        for (int k0 = 0; k0 < H_; k0 += 4) {
            float xr[8][4];
#pragma unroll
            for (int i = 0; i < 8; i++) {
                float4 v = *(float4*)&xs[(trow * 8 + i) * XPAD + k0];
                xr[i][0] = v.x; xr[i][1] = v.y; xr[i][2] = v.z; xr[i][3] = v.w;
            }
#pragma unroll
            for (int kk = 0; kk < 4; kk++) {
                float4 w0 = *(float4*)&ws[(k0 + kk) * 256 + tcol * 8];
                float4 w1 = *(float4*)&ws[(k0 + kk) * 256 + tcol * 8 + 4];
                float wr[8] = {w0.x, w0.y, w0.z, w0.w, w1.x, w1.y, w1.z, w1.w};
#pragma unroll
                for (int i = 0; i < 8; i++)
#pragma unroll
                    for (int j = 0; j < 8; j++)
                        acc[i][j] += xr[i][kk] * wr[j];
            }
        }

        // V (cols 128..255): direct row-major store
        if (tcol >= 16) {
            const int hb = (tcol - 16) * 8;
#pragma unroll
            for (int i = 0; i < 8; i++) {
                size_t key = (size_t)g * T_ + trow * 8 + i;
                float* dst = &g_V[((size_t)b * GT_ + key) * H_ + hb];
                *(float4*)dst       = make_float4(acc[i][0], acc[i][1], acc[i][2], acc[i][3]);
                *(float4*)(dst + 4) = make_float4(acc[i][4], acc[i][5], acc[i][6], acc[i][7]);
            }
        }
        __syncthreads();  // xs reads (compute) complete -> safe to reuse as staging
        // K (cols 0..127): stage into xs, then write transposed
        if (tcol < 16) {
#pragma unroll
            for (int i = 0; i < 8; i++)
#pragma unroll
                for (int j = 0; j < 8; j++)
                    xs[(trow * 8 + i) * XPAD + tcol * 8 + j] = acc[i][j];
        }
        __syncthreads();
        for (int idx = tid; idx < T_ * H_; idx += 256) {
            int h = idx >> 6;       // 0..127
            int key = idx & 63;     // 0..63 (coalesced)
            g_Kt[((size_t)b * H_ + h) * GT_ + (size_t)g * T_ + key] = xs[key * XPAD + h];
        }
    }
}

// ---------------------------------------------------------------------------
// Kernel 2: attention per batch.  256 threads, ~105 KB smem -> 2 CTAs/SM.
// Phase A: S = Q K^T per 128-key chunk, mask->-inf, write raw S to A region,
//          accumulate rowsum of exp(S) (no max subtraction: |S| <= ~63, safe).
// Phase C: re-read S, write P = exp(S)/l, accumulate O = P V, write O.
// ---------------------------------------------------------------------------
__global__ void __launch_bounds__(256, 2)
k_attn(const void* __restrict__ mask, float* __restrict__ out) {
    extern __shared__ float sm[];
    float* qs = sm;                          // [64][QPAD]  (phase C: P tile)
    float* ks = sm + T_ * QPAD;              // [128][128]  (phase C: V tile)
    float* red = ks + H_ * H_;               // [64*16]
    float* invl = red + T_ * 16;             // [64]
    unsigned char* ms = (unsigned char*)(invl + T_);  // [64*64]

    const int b = blockIdx.x;
    const int tid = threadIdx.x;
    const int tq = tid >> 4;   // 16 groups * 4 q rows
    const int tk = tid & 15;   // 16 groups * 8 keys (phase A) / 8 h (phase C)

    float* Ab = out + (size_t)B_ * T_ * H_ + (size_t)b * T_ * GT_;

    // Stage Q and mask (mask dtype per g_maskKind)
    const float* qg = g_Q + (size_t)b * T_ * H_;
    for (int f = tid; f < T_ * H_ / 4; f += 256) {
        int r = f >> 5, h4 = f & 31;
        *(float4*)&qs[r * QPAD + h4 * 4] = ((const float4*)qg)[f];
    }
    {
        const size_t base = (size_t)b * T_ * T_;
        const int kind = g_maskKind;
        if (kind == 1) {
            const int* mg = (const int*)mask + base;
            for (int f = tid; f < T_ * T_; f += 256)
                ms[f] = (unsigned char)(mg[f] != 0);
        } else if (kind == 2) {
            const float* mg = (const float*)mask + base;
            for (int f = tid; f < T_ * T_; f += 256)
                ms[f] = (unsigned char)(mg[f] != 0.0f);
        } else {
            const unsigned char* mg = (const unsigned char*)mask + base;
            for (int f = tid; f < T_ * T_; f += 256)
                ms[f] = mg[f];
        }
    }
    __syncthreads();

    // Per-thread mask bits: key-in-chunk = tk*8+j, mask col = (tk*8+j) % 64,
    // identical for every chunk (chunk size 128 = 2*T_).
    unsigned mbits[4];
#pragma unroll
    for (int i = 0; i < 4; i++) {
        int q = tq * 4 + i;
        unsigned m = 0;
#pragma unroll
        for (int j = 0; j < 8; j++) {
            int col = (tk * 8 + j) & 63;
            if (ms[q * 64 + col]) m |= (1u << j);
        }
        mbits[i] = m;
    }

    const float NEG_INF = __int_as_float(0xff800000u);
    float lsum[4] = {0.f, 0.f, 0.f, 0.f};
    const float* ktg = g_Kt + (size_t)b * H_ * GT_;

    for (int c = 0; c < 16; c++) {
        __syncthreads();
        for (int f = tid; f < H_ * 128 / 4; f += 256) {
            int h = f >> 5, k4 = f & 31;
            *(float4*)&ks[h * 128 + k4 * 4] =
                *(const float4*)&ktg[(size_t)h * GT_ + c * 128 + k4 * 4];
        }
        __syncthreads();

        float sc[4][8];
#pragma unroll
        for (int i = 0; i < 4; i++)
#pragma unroll
            for (int j = 0; j < 8; j++) sc[i][j] = 0.f;

        for (int h0 = 0; h0 < H_; h0 += 4) {
            float qr[4][4];
#pragma unroll
            for (int i = 0; i < 4; i++) {
                float4 v = *(float4*)&qs[(tq * 4 + i) * QPAD + h0];
                qr[i][0] = v.x; qr[i][1] = v.y; qr[i][2] = v.z; qr[i][3] = v.w;
            }
#pragma unroll
            for (int hh = 0; hh < 4; hh++) {
                float4 k0v = *(float4*)&ks[(h0 + hh) * 128 + tk * 8];
                float4 k1v = *(float4*)&ks[(h0 + hh) * 128 + tk * 8 + 4];
                float kr[8] = {k0v.x, k0v.y, k0v.z, k0v.w, k1v.x, k1v.y, k1v.z, k1v.w};
#pragma unroll
                for (int i = 0; i < 4; i++)
#pragma unroll
                    for (int j = 0; j < 8; j++)
                        sc[i][j] += qr[i][hh] * kr[j];
            }
        }
#pragma unroll
        for (int i = 0; i < 4; i++) {
            int q = tq * 4 + i;
#pragma unroll
            for (int j = 0; j < 8; j++) {
                if ((mbits[i] >> j) & 1) sc[i][j] = NEG_INF;
                lsum[i] += __expf(sc[i][j]);
            }
            float* dst = &Ab[(size_t)q * GT_ + c * 128 + tk * 8];
            *(float4*)dst       = make_float4(sc[i][0], sc[i][1], sc[i][2], sc[i][3]);
            *(float4*)(dst + 4) = make_float4(sc[i][4], sc[i][5], sc[i][6], sc[i][7]);
        }
    }

    // Row-sum reduction -> 1/l
#pragma unroll
    for (int i = 0; i < 4; i++) red[(tq * 4 + i) * 16 + tk] = lsum[i];
    __syncthreads();
    if (tid < 64) {
        float s = 0.f;
#pragma unroll
        for (int t = 0; t < 16; t++) s += red[tid * 16 + t];
        invl[tid] = 1.0f / s;
    }

    // ---------------- Phase C ----------------
    float* ps = qs;   // reuse Q tile as P tile
    float* vs = ks;   // reuse K tile as V tile
    const float* vg = g_V + (size_t)b * GT_ * H_;
    const int th = tk;

    float oacc[4][8];
#pragma unroll
    for (int i = 0; i < 4; i++)
#pragma unroll
        for (int j = 0; j < 8; j++) oacc[i][j] = 0.f;

    for (int c = 0; c < 16; c++) {
        __syncthreads();
        for (int f = tid; f < 128 * H_ / 4; f += 256) {
            int key = f >> 5, h4 = f & 31;
            *(float4*)&vs[key * 128 + h4 * 4] =
                *(const float4*)&vg[((size_t)(c * 128 + key)) * H_ + h4 * 4];
        }
        for (int f = tid; f < T_ * 128 / 4; f += 256) {
            int q = f >> 5, k4 = f & 31;
            float* gaddr = &Ab[(size_t)q * GT_ + c * 128 + k4 * 4];
            float4 v = *(float4*)gaddr;
            float il = invl[q];
            v.x = __expf(v.x) * il;
            v.y = __expf(v.y) * il;
            v.z = __expf(v.z) * il;
            v.w = __expf(v.w) * il;
            *(float4*)gaddr = v;
            *(float4*)&ps[q * QPAD + k4 * 4] = v;
        }
        __syncthreads();

        for (int kk0 = 0; kk0 < 128; kk0 += 4) {
            float pr[4][4];
#pragma unroll
            for (int i = 0; i < 4; i++) {
                float4 v = *(float4*)&ps[(tq * 4 + i) * QPAD + kk0];
                pr[i][0] = v.x; pr[i][1] = v.y; pr[i][2] = v.z; pr[i][3] = v.w;
            }
#pragma unroll
            for (int u = 0; u < 4; u++) {
                float4 v0 = *(float4*)&vs[(kk0 + u) * 128 + th * 8];
                float4 v1 = *(float4*)&vs[(kk0 + u) * 128 + th * 8 + 4];
                float vr[8] = {v0.x, v0.y, v0.z, v0.w, v1.x, v1.y, v1.z, v1.w};
#pragma unroll
                for (int i = 0; i < 4; i++)
#pragma unroll
                    for (int j = 0; j < 8; j++)
                        oacc[i][j] += pr[i][u] * vr[j];
            }
        }
    }

#pragma unroll
    for (int i = 0; i < 4; i++) {
        int q = tq * 4 + i;
        float* dst = &out[((size_t)b * T_ + q) * H_ + th * 8];
        *(float4*)dst       = make_float4(oacc[i][0], oacc[i][1], oacc[i][2], oacc[i][3]);
        *(float4*)(dst + 4) = make_float4(oacc[i][4], oacc[i][5], oacc[i][6], oacc[i][7]);
    }
}

// ---------------------------------------------------------------------------
static const int SMEM_Q  = (H_ * H_ + T_ * XPAD) * 4;                 //  99328
static const int SMEM_KV = (H_ * 256 + T_ * XPAD) * 4;                // 164864
static const int SMEM_AT = (T_ * QPAD + H_ * H_ + T_ * 16 + T_) * 4 + T_ * T_; // 107776

extern "C" void kernel_launch(void* const* d_in, const int* in_sizes, int n_in,
                              void* d_out, int out_size) {
    (void)in_sizes; (void)n_in; (void)out_size;
    const float* node  = (const float*)d_in[0];
    const float* neigh = (const float*)d_in[1];
    const void*  mask  = d_in[2];
    const float* Wq = (const float*)d_in[3];
    const float* Wk = (const float*)d_in[4];
    const float* Wv = (const float*)d_in[5];
    float* out = (float*)d_out;

    // One-time attribute opt-in (first call happens before graph capture).
    static bool inited = false;
    if (!inited) {
        cudaFuncSetAttribute(k_qproj,  cudaFuncAttributeMaxDynamicSharedMemorySize, SMEM_Q);
        cudaFuncSetAttribute(k_kvproj, cudaFuncAttributeMaxDynamicSharedMemorySize, SMEM_KV);
        cudaFuncSetAttribute(k_attn,   cudaFuncAttributeMaxDynamicSharedMemorySize, SMEM_AT);
        inited = true;
    }

    k_detect_mask<<<1, 256>>>((const unsigned*)mask);
    k_qproj<<<B_, 256, SMEM_Q>>>(node, Wq);
    k_kvproj<<<dim3(8, B_), 256, SMEM_KV>>>(node, neigh, Wk, Wv);
    k_attn<<<B_, 256, SMEM_AT>>>(mask, out);
}